// round 13
// baseline (speedup 1.0000x reference)
#include <cuda_runtime.h>

// Shapes (fixed):
//   points          (B, N, 3)  f32
//   point_features  (B, N, C)  f32
//   boxes3d         (B, M, 7)  f32  (cx, cy, cz_bottom, dx, dy, dz, rz)
// Output d_out:
//   pooled_features (B, M, S, 3+C) f32   [+ pooled_empty_flag (B,M) at tail if room]
#define BB    4
#define NPTS  16384
#define MBOX  128
#define CFEAT 128
#define SSAMP 512
#define ROW   (3 + CFEAT)        // 131
#define NBOX  (BB * MBOX)        // 512
#define NSEG  16                 // segments per box
#define SEGPTS (NPTS / NSEG)     // 1024 points per segment
#define BOXG  4                  // boxes per scan CTA

// Cross-kernel scratch (device globals — no allocation).
__device__ int g_seg_idx[NBOX * NSEG * SSAMP];   // 16 MB
__device__ int g_scnt[NBOX * NSEG];

// ============================ Kernel 1: segmented scan ============================
// (unchanged from R12 — register-resident points, shfl-scan compaction)
__global__ __launch_bounds__(256)
void scan_kernel(const float* __restrict__ points,
                 const float* __restrict__ boxes)
{
    __shared__ int s_wcnt[2][8];           // double-buffered per-warp counts

    const int gid  = blockIdx.x;           // ((b*32 + grp) << 4) | seg
    const int seg  = gid & 15;
    const int grp  = (gid >> 4) & 31;
    const int b    = gid >> 9;
    const int box0 = b * MBOX + grp * BOXG;
    const int tid  = threadIdx.x;
    const int wid  = tid >> 5;
    const int lane = tid & 31;

    const float4* src4 = reinterpret_cast<const float4*>(
        points + (size_t)b * NPTS * 3 + (size_t)seg * SEGPTS * 3);
    const float4 v0 = src4[3 * tid + 0];
    const float4 v1 = src4[3 * tid + 1];
    const float4 v2 = src4[3 * tid + 2];
    const float px[4] = { v0.x, v0.w, v1.z, v2.y };
    const float py[4] = { v0.y, v1.x, v1.w, v2.z };
    const float pz[4] = { v0.z, v1.y, v2.x, v2.w };

    int pb = 0;
    for (int bxi = 0; bxi < BOXG; bxi++) {
        const int box_id = box0 + bxi;
        const float* bx = boxes + box_id * 7;
        const float cx  = bx[0];
        const float cy  = bx[1];
        const float dxh = 0.5f * bx[3];
        const float dyh = 0.5f * bx[4];
        const float dzh = 0.5f * bx[5];
        const float cz  = bx[2] + dzh;
        const float rz  = bx[6];
        const float cosa = cosf(-rz);      // replicate reference op order
        const float sina = sinf(-rz);

        unsigned m = 0;
        #pragma unroll
        for (int e = 0; e < 4; e++) {
            const float sx = px[e] - cx;
            const float sy = py[e] - cy;
            const float lx = sx * cosa - sy * sina;
            const float ly = sx * sina + sy * cosa;
            const bool in =
                (fabsf(pz[e] - cz) <= dzh) &&
                (lx > -dxh) && (lx < dxh) &&
                (ly > -dyh) && (ly < dyh);
            m |= (unsigned)in << e;
        }
        const int c = __popc(m);

        int sc = c;
        #pragma unroll
        for (int off = 1; off < 32; off <<= 1) {
            const int n = __shfl_up_sync(0xffffffffu, sc, off);
            if (lane >= off) sc += n;
        }
        if (lane == 31) s_wcnt[pb][wid] = sc;
        __syncthreads();

        int wbase = 0, total = 0;
        #pragma unroll
        for (int w = 0; w < 8; w++) {
            const int x = s_wcnt[pb][w];
            if (w < wid) wbase += x;
            total += x;
        }
        const int base = wbase + (sc - c);

        int* my_idx = g_seg_idx + (box_id * NSEG + seg) * SSAMP;
        #pragma unroll
        for (int e = 0; e < 4; e++) {
            if ((m >> e) & 1u) {
                const int pos = base + __popc(m & ((1u << e) - 1u));
                if (pos < SSAMP) my_idx[pos] = seg * SEGPTS + 4 * tid + e;
            }
        }
        if (tid == 0) g_scnt[box_id * NSEG + seg] = total;
        pb ^= 1;
    }
}

// ============================ Kernel 2: gather + write ============================
// One CTA per (box, quarter): 128 rows. Direct stores (R10 structure) with
// 4-row load batching for MLP; xyz served from smem.
__global__ __launch_bounds__(256)
void gather_kernel(const float* __restrict__ points,
                   const float* __restrict__ feats,
                   float* __restrict__ out,
                   float* __restrict__ flags)
{
    __shared__ int   s_rowidx[128];        // resolved point index per output row
    __shared__ float s_xyz[128 * 3];       // xyz per output row
    __shared__ int   s_cnt;

    const int box_id = blockIdx.x >> 2;
    const int q      = blockIdx.x & 3;
    const int b      = box_id / MBOX;
    const int tid    = threadIdx.x;
    const int wid    = tid >> 5;
    const int lane   = tid & 31;

    // --- prologue: resolve indices + xyz once per row (threads 0..127) ---
    if (tid < 128) {
        const int* sc = g_scnt + box_id * NSEG;
        int pre[NSEG + 1];
        pre[0] = 0;
        #pragma unroll
        for (int k = 0; k < NSEG; k++) pre[k + 1] = pre[k] + sc[k];
        int cnt = pre[NSEG];
        if (cnt > SSAMP) cnt = SSAMP;
        if (tid == 0) s_cnt = cnt;
        if (cnt > 0) {
            const int s = q * 128 + tid;
            const int j = s % cnt;                 // global in-box rank (< 512)
            int k = 0;
            #pragma unroll
            for (int kk = 1; kk < NSEG; kk++)
                if (j >= pre[kk]) k = kk;
            const int idx = g_seg_idx[(box_id * NSEG + k) * SSAMP + (j - pre[k])];
            s_rowidx[tid] = idx;
            const float* p = points + (size_t)b * NPTS * 3 + idx * 3;
            s_xyz[tid * 3 + 0] = p[0];
            s_xyz[tid * 3 + 1] = p[1];
            s_xyz[tid * 3 + 2] = p[2];
        }
    }
    __syncthreads();
    const int cnt = s_cnt;

    float* oq = out + (size_t)box_id * (SSAMP * ROW) + q * 128 * ROW;  // 16B-aligned
    if (cnt == 0) {
        const float4 z = make_float4(0.f, 0.f, 0.f, 0.f);
        float4* o4 = reinterpret_cast<float4*>(oq);
        for (int i = tid; i < 4192; i += 256) __stcs(&o4[i], z);
        if (q == 0 && tid == 0 && flags != nullptr) flags[box_id] = 1.0f;
        return;
    }

    const float* fb = feats + (size_t)b * NPTS * CFEAT;

    // warp-per-row, 16 rows per warp, batched 4 at a time for MLP
    #pragma unroll
    for (int t = 0; t < 4; t++) {
        const int r0 = wid * 16 + t * 4;           // local rows r0..r0+3
        int    idx[4];
        float4 f[4];
        #pragma unroll
        for (int j = 0; j < 4; j++) idx[j] = s_rowidx[r0 + j];
        #pragma unroll
        for (int j = 0; j < 4; j++)                // 4 independent LDG.128 in flight
            f[j] = reinterpret_cast<const float4*>(fb + (size_t)idx[j] * CFEAT)[lane];
        #pragma unroll
        for (int j = 0; j < 4; j++) {
            float* orow = oq + (r0 + j) * ROW;
            __stcs(orow + 3 + 4 * lane + 0, f[j].x);
            __stcs(orow + 3 + 4 * lane + 1, f[j].y);
            __stcs(orow + 3 + 4 * lane + 2, f[j].z);
            __stcs(orow + 3 + 4 * lane + 3, f[j].w);
            if (lane < 3) __stcs(orow + lane, s_xyz[(r0 + j) * 3 + lane]);
        }
    }
    if (q == 0 && tid == 0 && flags != nullptr) flags[box_id] = 0.0f;
}

extern "C" void kernel_launch(void* const* d_in, const int* in_sizes, int n_in,
                              void* d_out, int out_size)
{
    const float* points = (const float*)d_in[0];   // (B, N, 3)
    const float* feats  = (const float*)d_in[1];   // (B, N, C)
    const float* boxes  = (const float*)d_in[2];   // (B, M, 7)

    float* out = (float*)d_out;
    const size_t feat_elems = (size_t)NBOX * SSAMP * ROW;   // 34,340,864
    float* flags = nullptr;
    if ((size_t)out_size >= feat_elems + (size_t)NBOX)
        flags = out + feat_elems;

    scan_kernel<<<(NBOX / BOXG) * NSEG, 256>>>(points, boxes);
    gather_kernel<<<NBOX * 4, 256>>>(points, feats, out, flags);
}

// round 14
// speedup vs baseline: 1.3592x; 1.3592x over previous
#include <cuda_runtime.h>

// Shapes (fixed):
//   points          (B, N, 3)  f32
//   point_features  (B, N, C)  f32
//   boxes3d         (B, M, 7)  f32  (cx, cy, cz_bottom, dx, dy, dz, rz)
// Output d_out:
//   pooled_features (B, M, S, 3+C) f32   [+ pooled_empty_flag (B,M) at tail if room]
#define BB    4
#define NPTS  16384
#define MBOX  128
#define CFEAT 128
#define SSAMP 512
#define ROW   (3 + CFEAT)        // 131
#define NBOX  (BB * MBOX)        // 512
#define NSEG  16                 // segments per box
#define SEGPTS (NPTS / NSEG)     // 1024 points per segment
#define BOXG  4                  // boxes per scan CTA
#define QCTA  8                  // gather CTAs per box (64 rows each)

// Cross-kernel scratch (device globals — no allocation).
__device__ int g_seg_idx[NBOX * NSEG * SSAMP];   // 16 MB
__device__ int g_scnt[NBOX * NSEG];

// ============================ Kernel 1: segmented scan ============================
// (R12 version — register-resident points, shfl-scan ordered compaction)
__global__ __launch_bounds__(256)
void scan_kernel(const float* __restrict__ points,
                 const float* __restrict__ boxes)
{
    __shared__ int s_wcnt[2][8];           // double-buffered per-warp counts

    const int gid  = blockIdx.x;           // ((b*32 + grp) << 4) | seg
    const int seg  = gid & 15;
    const int grp  = (gid >> 4) & 31;
    const int b    = gid >> 9;
    const int box0 = b * MBOX + grp * BOXG;
    const int tid  = threadIdx.x;
    const int wid  = tid >> 5;
    const int lane = tid & 31;

    const float4* src4 = reinterpret_cast<const float4*>(
        points + (size_t)b * NPTS * 3 + (size_t)seg * SEGPTS * 3);
    const float4 v0 = src4[3 * tid + 0];
    const float4 v1 = src4[3 * tid + 1];
    const float4 v2 = src4[3 * tid + 2];
    const float px[4] = { v0.x, v0.w, v1.z, v2.y };
    const float py[4] = { v0.y, v1.x, v1.w, v2.z };
    const float pz[4] = { v0.z, v1.y, v2.x, v2.w };

    int pb = 0;
    for (int bxi = 0; bxi < BOXG; bxi++) {
        const int box_id = box0 + bxi;
        const float* bx = boxes + box_id * 7;
        const float cx  = bx[0];
        const float cy  = bx[1];
        const float dxh = 0.5f * bx[3];
        const float dyh = 0.5f * bx[4];
        const float dzh = 0.5f * bx[5];
        const float cz  = bx[2] + dzh;
        const float rz  = bx[6];
        const float cosa = cosf(-rz);      // replicate reference op order
        const float sina = sinf(-rz);

        unsigned m = 0;
        #pragma unroll
        for (int e = 0; e < 4; e++) {
            const float sx = px[e] - cx;
            const float sy = py[e] - cy;
            const float lx = sx * cosa - sy * sina;
            const float ly = sx * sina + sy * cosa;
            const bool in =
                (fabsf(pz[e] - cz) <= dzh) &&
                (lx > -dxh) && (lx < dxh) &&
                (ly > -dyh) && (ly < dyh);
            m |= (unsigned)in << e;
        }
        const int c = __popc(m);

        int sc = c;
        #pragma unroll
        for (int off = 1; off < 32; off <<= 1) {
            const int n = __shfl_up_sync(0xffffffffu, sc, off);
            if (lane >= off) sc += n;
        }
        if (lane == 31) s_wcnt[pb][wid] = sc;
        __syncthreads();

        int wbase = 0, total = 0;
        #pragma unroll
        for (int w = 0; w < 8; w++) {
            const int x = s_wcnt[pb][w];
            if (w < wid) wbase += x;
            total += x;
        }
        const int base = wbase + (sc - c);

        int* my_idx = g_seg_idx + (box_id * NSEG + seg) * SSAMP;
        #pragma unroll
        for (int e = 0; e < 4; e++) {
            if ((m >> e) & 1u) {
                const int pos = base + __popc(m & ((1u << e) - 1u));
                if (pos < SSAMP) my_idx[pos] = seg * SEGPTS + 4 * tid + e;
            }
        }
        if (tid == 0) g_scnt[box_id * NSEG + seg] = total;
        pb ^= 1;
    }
}

// ============================ Kernel 2: gather + write ============================
// One CTA per (box, eighth): 64 rows. R10 structure: conflict-free smem tiles
// swept out as aligned STG.128 streaming stores. 2 tiles, 3 barriers.
__global__ __launch_bounds__(256)
void gather_kernel(const float* __restrict__ points,
                   const float* __restrict__ feats,
                   float* __restrict__ out,
                   float* __restrict__ flags)
{
    __shared__ float s_tile[32 * ROW];     // 32 rows x 131 floats = 16768 B
    __shared__ int   s_rowidx[64];         // resolved point index per output row
    __shared__ int   s_cnt;

    const int box_id = blockIdx.x >> 3;
    const int q      = blockIdx.x & 7;
    const int b      = box_id / MBOX;
    const int tid    = threadIdx.x;
    const int wid    = tid >> 5;
    const int lane   = tid & 31;

    // --- prologue: resolve indices once per row (threads 0..63) ---
    if (tid < 64) {
        const int* sc = g_scnt + box_id * NSEG;
        int pre[NSEG + 1];
        pre[0] = 0;
        #pragma unroll
        for (int k = 0; k < NSEG; k++) pre[k + 1] = pre[k] + sc[k];
        int cnt = pre[NSEG];
        if (cnt > SSAMP) cnt = SSAMP;
        if (tid == 0) s_cnt = cnt;
        if (cnt > 0) {
            const int s = q * 64 + tid;
            const int j = s % cnt;                 // global in-box rank (< 512)
            int k = 0;
            #pragma unroll
            for (int kk = 1; kk < NSEG; kk++)
                if (j >= pre[kk]) k = kk;
            s_rowidx[tid] = g_seg_idx[(box_id * NSEG + k) * SSAMP + (j - pre[k])];
        }
    }
    __syncthreads();
    const int cnt = s_cnt;

    float* oq = out + (size_t)box_id * (SSAMP * ROW) + q * 64 * ROW;  // 16B-aligned
    if (cnt == 0) {
        const float4 z = make_float4(0.f, 0.f, 0.f, 0.f);
        float4* o4 = reinterpret_cast<float4*>(oq);
        for (int i = tid; i < 2096; i += 256) __stcs(&o4[i], z);   // 64*131/4
        if (q == 0 && tid == 0 && flags != nullptr) flags[box_id] = 1.0f;
        return;
    }

    const float* pts = points + (size_t)b * NPTS * 3;
    const float* fb  = feats  + (size_t)b * NPTS * CFEAT;

    #pragma unroll
    for (int t = 0; t < 2; t++) {          // 2 tiles of 32 rows
        if (t) __syncthreads();            // previous tile fully drained
        // --- gather 32 rows into smem; warp w handles rows w*4..w*4+3 ---
        #pragma unroll
        for (int i = 0; i < 4; i++) {
            const int r   = wid * 4 + i;           // local row in tile
            const int idx = s_rowidx[t * 32 + r];  // broadcast LDS
            const float* frow = fb + (size_t)idx * CFEAT;
            float* srow = s_tile + r * ROW;
            // coalesced map: lane l -> columns l,32+l,64+l,96+l; STS bank
            // (3r+3+l)%32: conflict-free
            #pragma unroll
            for (int p = 0; p < 4; p++)
                srow[3 + 32 * p + lane] = frow[32 * p + lane];
            if (lane < 3) srow[lane] = pts[idx * 3 + lane];
        }
        __syncthreads();
        // --- aligned streaming write: 4192 floats = 1048 float4 ---
        const float4* s4 = reinterpret_cast<const float4*>(s_tile);
        float4* o4 = reinterpret_cast<float4*>(oq + t * 32 * ROW);
        for (int i = tid; i < 1048; i += 256) __stcs(&o4[i], s4[i]);
    }
    if (q == 0 && tid == 0 && flags != nullptr) flags[box_id] = 0.0f;
}

extern "C" void kernel_launch(void* const* d_in, const int* in_sizes, int n_in,
                              void* d_out, int out_size)
{
    const float* points = (const float*)d_in[0];   // (B, N, 3)
    const float* feats  = (const float*)d_in[1];   // (B, N, C)
    const float* boxes  = (const float*)d_in[2];   // (B, M, 7)

    float* out = (float*)d_out;
    const size_t feat_elems = (size_t)NBOX * SSAMP * ROW;   // 34,340,864
    float* flags = nullptr;
    if ((size_t)out_size >= feat_elems + (size_t)NBOX)
        flags = out + feat_elems;

    scan_kernel<<<(NBOX / BOXG) * NSEG, 256>>>(points, boxes);
    gather_kernel<<<NBOX * QCTA, 256>>>(points, feats, out, flags);
}